// round 1
// baseline (speedup 1.0000x reference)
#include <cuda_runtime.h>

// ---------------------------------------------------------------------------
// Fused single-head attention, fp32 in/out, TF32 tensor-core GEMMs.
//   B=8, S=2048, D=1024
//   Q = x@Wq + bq ; K = x@Wk + bk ; V = x@Wv + bv
//   S = Q@K^T / sqrt(D) ; A = softmax(S, axis=-1) ; O = A@V
// ---------------------------------------------------------------------------

#define BATCH 8
#define SEQ   2048
#define DIM   1024
#define MTOT  (BATCH * SEQ)          // 16384

#define BM 128
#define BN 128
#define BK 16
#define NTHREADS 256

// scratch (device globals: no cudaMalloc allowed)
__device__ float g_Q[(size_t)MTOT * DIM];
__device__ float g_K[(size_t)MTOT * DIM];
__device__ float g_V[(size_t)MTOT * DIM];
__device__ float g_S[(size_t)BATCH * SEQ * SEQ];

__device__ __forceinline__ unsigned f2tf32(float f) {
    unsigned r;
    asm("cvt.rna.tf32.f32 %0, %1;" : "=r"(r) : "f"(f));
    return r;
}

__device__ __forceinline__ void mma8(float* c, const unsigned* a, const unsigned* b) {
    asm volatile(
        "mma.sync.aligned.m16n8k8.row.col.f32.tf32.tf32.f32 "
        "{%0,%1,%2,%3}, {%4,%5,%6,%7}, {%8,%9}, {%0,%1,%2,%3};"
        : "+f"(c[0]), "+f"(c[1]), "+f"(c[2]), "+f"(c[3])
        : "r"(a[0]), "r"(a[1]), "r"(a[2]), "r"(a[3]),
          "r"(b[0]), "r"(b[1]));
}

// C[M,N] = alpha * A[M,K] @ op(B) + bias
//   TRANS_B = false : B is [K,N] row-major  (NN)
//   TRANS_B = true  : B is [N,K] row-major  (NT, i.e. A @ B^T)
// M % 128 == 0, N % 128 == 0, K % 16 == 0 assumed.
template <bool TRANS_B>
__global__ void __launch_bounds__(NTHREADS)
gemm_tf32(const float* __restrict__ A, const float* __restrict__ Bm,
          const float* __restrict__ bias, float* __restrict__ C,
          int M, int N, int K, float alpha,
          long long sA, long long sB, long long sC)
{
    A  += (long long)blockIdx.z * sA;
    Bm += (long long)blockIdx.z * sB;
    C  += (long long)blockIdx.z * sC;

    const int bm = blockIdx.y * BM;
    const int bn = blockIdx.x * BN;
    const int tid  = threadIdx.x;
    const int lane = tid & 31;
    const int wid  = tid >> 5;
    const int warp_m = wid & 3;   // 4 warps over M (32 rows each)
    const int warp_n = wid >> 2;  // 2 warps over N (64 cols each)
    const int g = lane >> 2;      // group id 0..7
    const int t = lane & 3;       // thread-in-group 0..3

    // SMEM: A tile [BM][16] padded stride 20 (K-contiguous)
    //       B tile: NT -> [BN][16] stride 20 ; NN -> [16][BN] stride 136
    constexpr int BS_SZ = TRANS_B ? (BN * 20) : (BK * 136);
    __shared__ float As[2][BM * 20];
    __shared__ float Bs[2][BS_SZ];

    // loader mapping
    const int a_row = tid >> 2;            // 0..63 (and +64)
    const int a_c4  = (tid & 3) * 4;       // k offset 0,4,8,12
    const int b_kr  = tid >> 5;            // 0..7 (and +8)     (NN)
    const int b_cn  = (tid & 31) * 4;      // n offset           (NN)

    const float* Aptr0 = A + (long long)(bm + a_row) * K + a_c4;
    const float* Aptr1 = A + (long long)(bm + a_row + 64) * K + a_c4;
    const float* Bptr0;
    const float* Bptr1;
    if (TRANS_B) {
        Bptr0 = Bm + (long long)(bn + a_row) * K + a_c4;
        Bptr1 = Bm + (long long)(bn + a_row + 64) * K + a_c4;
    } else {
        Bptr0 = Bm + (long long)b_kr * N + bn + b_cn;
        Bptr1 = Bm + (long long)(b_kr + 8) * N + bn + b_cn;
    }

    float4 ra[2][2], rb[2][2];
    float acc[2][8][4];
#pragma unroll
    for (int i = 0; i < 2; ++i)
#pragma unroll
        for (int j = 0; j < 8; ++j)
#pragma unroll
            for (int q = 0; q < 4; ++q) acc[i][j][q] = 0.f;

    const int nk = K / BK;

    auto load_stage = [&](int kt, int s) {
        const int koff = kt * BK;
        ra[s][0] = *(const float4*)(Aptr0 + koff);
        ra[s][1] = *(const float4*)(Aptr1 + koff);
        if (TRANS_B) {
            rb[s][0] = *(const float4*)(Bptr0 + koff);
            rb[s][1] = *(const float4*)(Bptr1 + koff);
        } else {
            rb[s][0] = *(const float4*)(Bptr0 + (long long)koff * N);
            rb[s][1] = *(const float4*)(Bptr1 + (long long)koff * N);
        }
    };

    auto cvt4 = [](float4 v) {
        float4 r;
        r.x = __uint_as_float(f2tf32(v.x));
        r.y = __uint_as_float(f2tf32(v.y));
        r.z = __uint_as_float(f2tf32(v.z));
        r.w = __uint_as_float(f2tf32(v.w));
        return r;
    };

    auto store_stage = [&](int buf, int s) {
        *(float4*)&As[buf][a_row * 20 + a_c4]        = cvt4(ra[s][0]);
        *(float4*)&As[buf][(a_row + 64) * 20 + a_c4] = cvt4(ra[s][1]);
        if (TRANS_B) {
            *(float4*)&Bs[buf][a_row * 20 + a_c4]        = cvt4(rb[s][0]);
            *(float4*)&Bs[buf][(a_row + 64) * 20 + a_c4] = cvt4(rb[s][1]);
        } else {
            *(float4*)&Bs[buf][b_kr * 136 + b_cn]       = cvt4(rb[s][0]);
            *(float4*)&Bs[buf][(b_kr + 8) * 136 + b_cn] = cvt4(rb[s][1]);
        }
    };

    auto compute = [&](int buf) {
#pragma unroll
        for (int kk = 0; kk < BK; kk += 8) {
            unsigned af[2][4];
#pragma unroll
            for (int im = 0; im < 2; ++im) {
                const int r = warp_m * 32 + im * 16 + g;
                const float* p0 = &As[buf][r * 20 + kk + t];
                const float* p1 = &As[buf][(r + 8) * 20 + kk + t];
                af[im][0] = __float_as_uint(p0[0]);
                af[im][1] = __float_as_uint(p1[0]);
                af[im][2] = __float_as_uint(p0[4]);
                af[im][3] = __float_as_uint(p1[4]);
            }
            unsigned bf[8][2];
#pragma unroll
            for (int in_ = 0; in_ < 8; ++in_) {
                const int cn = warp_n * 64 + in_ * 8 + g;
                if (TRANS_B) {
                    const float* p = &Bs[buf][cn * 20 + kk + t];
                    bf[in_][0] = __float_as_uint(p[0]);
                    bf[in_][1] = __float_as_uint(p[4]);
                } else {
                    bf[in_][0] = __float_as_uint(Bs[buf][(kk + t) * 136 + cn]);
                    bf[in_][1] = __float_as_uint(Bs[buf][(kk + t + 4) * 136 + cn]);
                }
            }
#pragma unroll
            for (int im = 0; im < 2; ++im)
#pragma unroll
                for (int in_ = 0; in_ < 8; ++in_)
                    mma8(acc[im][in_], af[im], bf[in_]);
        }
    };

    // prologue: tile0 -> smem(buf0); tile1 -> regs(slot1)
    load_stage(0, 0);
    store_stage(0, 0);
    if (nk > 1) load_stage(1, 1);
    __syncthreads();

    for (int kt = 0; kt < nk; ++kt) {
        const int cur = kt & 1;
        if (kt + 2 < nk) load_stage(kt + 2, cur);       // tile kt+2 -> freed slot
        compute(cur);
        if (kt + 1 < nk) store_stage((kt + 1) & 1, (kt + 1) & 1);
        __syncthreads();
    }

    // epilogue
#pragma unroll
    for (int im = 0; im < 2; ++im) {
        const int r0 = bm + warp_m * 32 + im * 16 + g;
#pragma unroll
        for (int in_ = 0; in_ < 8; ++in_) {
            const int c0 = bn + warp_n * 64 + in_ * 8 + 2 * t;
            float bb0 = 0.f, bb1 = 0.f;
            if (bias) { bb0 = bias[c0]; bb1 = bias[c0 + 1]; }
            const long long i00 = (long long)r0 * N + c0;
            const long long i10 = (long long)(r0 + 8) * N + c0;
            float2 v0, v1;
            v0.x = acc[im][in_][0] * alpha + bb0;
            v0.y = acc[im][in_][1] * alpha + bb1;
            v1.x = acc[im][in_][2] * alpha + bb0;
            v1.y = acc[im][in_][3] * alpha + bb1;
            *(float2*)&C[i00] = v0;
            *(float2*)&C[i10] = v1;
        }
    }
}

// row softmax over 2048-wide rows, in place. grid = #rows, block = 256.
__global__ void __launch_bounds__(256)
softmax_rows(float* __restrict__ S)
{
    const int ncol = SEQ;
    const long long base = (long long)blockIdx.x * ncol;
    const int tid = threadIdx.x;
    const int lane = tid & 31;
    const int wid = tid >> 5;

    float v[8];
    float m = -1e30f;
#pragma unroll
    for (int i = 0; i < 8; ++i) {
        v[i] = S[base + tid + i * 256];
        m = fmaxf(m, v[i]);
    }
    __shared__ float red[8];
#pragma unroll
    for (int o = 16; o > 0; o >>= 1) m = fmaxf(m, __shfl_xor_sync(0xffffffffu, m, o));
    if (lane == 0) red[wid] = m;
    __syncthreads();
    float mr = red[0];
#pragma unroll
    for (int i = 1; i < 8; ++i) mr = fmaxf(mr, red[i]);
    __syncthreads();

    float s = 0.f;
#pragma unroll
    for (int i = 0; i < 8; ++i) {
        v[i] = expf(v[i] - mr);
        s += v[i];
    }
#pragma unroll
    for (int o = 16; o > 0; o >>= 1) s += __shfl_xor_sync(0xffffffffu, s, o);
    if (lane == 0) red[wid] = s;
    __syncthreads();
    float st = 0.f;
#pragma unroll
    for (int i = 0; i < 8; ++i) st += red[i];
    const float inv = 1.0f / st;
#pragma unroll
    for (int i = 0; i < 8; ++i)
        S[base + tid + i * 256] = v[i] * inv;
}

extern "C" void kernel_launch(void* const* d_in, const int* in_sizes, int n_in,
                              void* d_out, int out_size)
{
    (void)in_sizes; (void)n_in; (void)out_size;
    const float* x  = (const float*)d_in[0];
    const float* Wq = (const float*)d_in[1];
    const float* bq = (const float*)d_in[2];
    const float* Wk = (const float*)d_in[3];
    const float* bk = (const float*)d_in[4];
    const float* Wv = (const float*)d_in[5];
    const float* bv = (const float*)d_in[6];
    float* out = (float*)d_out;

    float *Qp, *Kp, *Vp, *Sp;
    cudaGetSymbolAddress((void**)&Qp, g_Q);
    cudaGetSymbolAddress((void**)&Kp, g_K);
    cudaGetSymbolAddress((void**)&Vp, g_V);
    cudaGetSymbolAddress((void**)&Sp, g_S);

    dim3 blk(NTHREADS);

    // QKV projections: [16384,1024] @ [1024,1024] + bias (NN)
    dim3 gqkv(DIM / BN, MTOT / BM, 1);
    gemm_tf32<false><<<gqkv, blk>>>(x, Wq, bq, Qp, MTOT, DIM, DIM, 1.0f, 0, 0, 0);
    gemm_tf32<false><<<gqkv, blk>>>(x, Wk, bk, Kp, MTOT, DIM, DIM, 1.0f, 0, 0, 0);
    gemm_tf32<false><<<gqkv, blk>>>(x, Wv, bv, Vp, MTOT, DIM, DIM, 1.0f, 0, 0, 0);

    // scores: per-batch Q @ K^T / sqrt(D)  (NT)
    dim3 gsc(SEQ / BN, SEQ / BM, BATCH);
    gemm_tf32<true><<<gsc, blk>>>(Qp, Kp, nullptr, Sp, SEQ, SEQ, DIM, 0.03125f,
                                  (long long)SEQ * DIM, (long long)SEQ * DIM,
                                  (long long)SEQ * SEQ);

    // softmax rows (B*S rows of length S)
    softmax_rows<<<BATCH * SEQ, 256>>>(Sp);

    // out: per-batch A @ V  (NN)
    dim3 gov(DIM / BN, SEQ / BM, BATCH);
    gemm_tf32<false><<<gov, blk>>>(Sp, Vp, nullptr, out, SEQ, DIM, SEQ, 1.0f,
                                   (long long)SEQ * SEQ, (long long)SEQ * DIM,
                                   (long long)SEQ * DIM);
}

// round 3
// speedup vs baseline: 1.1611x; 1.1611x over previous
#include <cuda_runtime.h>
#include <cstdint>

// ---------------------------------------------------------------------------
// Fused single-head attention, fp32 in/out. TF32 mma.sync GEMMs (sm_103 base),
// k-permuted operand storage for LDS.128 fragment loads, cp.async multistage.
//   B=8, S=2048, D=1024
// ---------------------------------------------------------------------------

#define BATCH 8
#define SEQ   2048
#define DIM   1024
#define MTOT  (BATCH * SEQ)      // 16384
#define N3    (3 * DIM)          // 3072

#define BM 128
#define BN 256
#define BK 16
#define NST 4
#define STAGE_BYTES 24576        // A 128*64B + B 256*64B
#define SMEM_DYN (NST * STAGE_BYTES)

// within-16 k permutation (involution): p(k) = (k%4)*4 + k/4
__host__ __device__ __forceinline__ int P16(int j) { return ((j & 3) << 2) | ((j >> 2) & 3); }
__host__ __device__ __forceinline__ int PERMC(int c) { return (c & ~15) | P16(c & 15); }

// scratch (device globals — no cudaMalloc allowed)
__device__ float g_QKV[(size_t)MTOT * N3];        // Q|K|V, ld = 3072, cols k-permuted
__device__ float g_S[(size_t)BATCH * SEQ * SEQ];  // aliased: xr before scores GEMM
__device__ float g_Vt[(size_t)MTOT * DIM];        // V^T per batch, cols k-permuted
__device__ float g_Wt[3 * (size_t)DIM * DIM];     // W^T rounded, cols k-permuted
__device__ float g_b3[N3];

__device__ __forceinline__ float rnaf(float f) {
    unsigned r;
    asm("cvt.rna.tf32.f32 %0, %1;" : "=r"(r) : "f"(f));
    return __uint_as_float(r);
}

__device__ __forceinline__ uint32_t smem_u32(const void* p) {
    uint32_t a;
    asm("{ .reg .u64 t; cvta.to.shared.u64 t, %1; cvt.u32.u64 %0, t; }" : "=r"(a) : "l"(p));
    return a;
}

__device__ __forceinline__ void cp_async16(uint32_t dst, const void* src) {
    asm volatile("cp.async.cg.shared.global [%0], [%1], 16;" :: "r"(dst), "l"(src) : "memory");
}
#define CP_COMMIT() asm volatile("cp.async.commit_group;" ::: "memory")
#define CP_WAIT2()  asm volatile("cp.async.wait_group 2;" ::: "memory")

__device__ __forceinline__ void mma8(float* c, const unsigned* a, const unsigned* b) {
    asm volatile(
        "mma.sync.aligned.m16n8k8.row.col.f32.tf32.tf32.f32 "
        "{%0,%1,%2,%3}, {%4,%5,%6,%7}, {%8,%9}, {%0,%1,%2,%3};"
        : "+f"(c[0]), "+f"(c[1]), "+f"(c[2]), "+f"(c[3])
        : "r"(a[0]), "r"(a[1]), "r"(a[2]), "r"(a[3]),
          "r"(b[0]), "r"(b[1]));
}

// ------------------------------ GEMM ---------------------------------------
// C[M,N](ldc) = alpha * A[M,K](lda) @ B[N,K](ldb)^T  (+bias, rna+perm if flag)
// A,B stored k-permuted (within 16-groups). K = nk*16, M%128==0, N%256==0.
__global__ void __launch_bounds__(256, 1)
gemm_nt(const float* __restrict__ A, const float* __restrict__ B,
        const float* __restrict__ bias, float* __restrict__ C,
        int lda, int ldb, int ldc, float alpha, int rna_perm, int nk,
        long long sA, long long sB, long long sC)
{
    extern __shared__ char smem[];
    A += (long long)blockIdx.z * sA;
    B += (long long)blockIdx.z * sB;
    C += (long long)blockIdx.z * sC;

    const int bm = blockIdx.y * BM;
    const int bn = blockIdx.x * BN;
    const int tid  = threadIdx.x;
    const int lane = tid & 31;
    const int wid  = tid >> 5;
    const int wm = wid & 1;      // 2 warps over M (64 rows)
    const int wn = wid >> 1;     // 4 warps over N (64 cols)
    const int g = lane >> 2;
    const int t = lane & 3;

    const uint32_t sb0 = smem_u32(smem);

    // producer mapping: A 512 chunks of 16B (2/thread), B 1024 chunks (4/thread)
    const int ac0 = tid * 2;
    const int bc0 = tid * 4;

    auto produce = [&](int i) {
        const int k0 = i * BK;
        const uint32_t st = sb0 + (uint32_t)(i & (NST - 1)) * STAGE_BYTES;
#pragma unroll
        for (int j = 0; j < 2; ++j) {
            const int c = ac0 + j, row = c >> 2, cc = c & 3;
            cp_async16(st + (uint32_t)(row * 64 + cc * 16),
                       A + (long long)(bm + row) * lda + k0 + cc * 4);
        }
#pragma unroll
        for (int j = 0; j < 4; ++j) {
            const int c = bc0 + j, row = c >> 2, cc = c & 3;
            cp_async16(st + 8192u + (uint32_t)(row * 64 + cc * 16),
                       B + (long long)(bn + row) * ldb + k0 + cc * 4);
        }
    };

    float acc[4][8][4];
#pragma unroll
    for (int i = 0; i < 4; ++i)
#pragma unroll
        for (int j = 0; j < 8; ++j)
#pragma unroll
            for (int q = 0; q < 4; ++q) acc[i][j][q] = 0.f;

#pragma unroll
    for (int s = 0; s < 3; ++s) {
        if (s < nk) produce(s);
        CP_COMMIT();
    }

    for (int i = 0; i < nk; ++i) {
        CP_WAIT2();
        __syncthreads();
        if (i + 3 < nk) produce(i + 3);
        CP_COMMIT();

        const char* st = smem + (size_t)(i & (NST - 1)) * STAGE_BYTES;
        const float4* Af = (const float4*)st;          // [128 rows][4 chunks]
        const float4* Bf = (const float4*)(st + 8192); // [256 rows][4 chunks]

        float4 bf[8];
#pragma unroll
        for (int nj = 0; nj < 8; ++nj)
            bf[nj] = Bf[(wn * 64 + nj * 8 + g) * 4 + t];

#pragma unroll
        for (int im = 0; im < 4; ++im) {
            const int r = wm * 64 + im * 16 + g;
            const float4 lo = Af[r * 4 + t];
            const float4 hi = Af[(r + 8) * 4 + t];
            unsigned a0[4] = { __float_as_uint(lo.x), __float_as_uint(hi.x),
                               __float_as_uint(lo.y), __float_as_uint(hi.y) };
            unsigned a1[4] = { __float_as_uint(lo.z), __float_as_uint(hi.z),
                               __float_as_uint(lo.w), __float_as_uint(hi.w) };
#pragma unroll
            for (int nj = 0; nj < 8; ++nj) {
                unsigned b0[2] = { __float_as_uint(bf[nj].x), __float_as_uint(bf[nj].y) };
                unsigned b1[2] = { __float_as_uint(bf[nj].z), __float_as_uint(bf[nj].w) };
                mma8(acc[im][nj], a0, b0);
                mma8(acc[im][nj], a1, b1);
            }
        }
    }

    // epilogue
#pragma unroll
    for (int im = 0; im < 4; ++im) {
        const int r0 = bm + wm * 64 + im * 16 + g;
#pragma unroll
        for (int nj = 0; nj < 8; ++nj) {
            const int c0 = bn + wn * 64 + nj * 8 + 2 * t;
            if (rna_perm) {
                const float b0 = bias ? __ldg(bias + c0) : 0.f;
                const float b1 = bias ? __ldg(bias + c0 + 1) : 0.f;
                const int pc0 = PERMC(c0), pc1 = PERMC(c0 + 1);
                C[(long long)r0 * ldc + pc0]       = rnaf(acc[im][nj][0] * alpha + b0);
                C[(long long)r0 * ldc + pc1]       = rnaf(acc[im][nj][1] * alpha + b1);
                C[(long long)(r0 + 8) * ldc + pc0] = rnaf(acc[im][nj][2] * alpha + b0);
                C[(long long)(r0 + 8) * ldc + pc1] = rnaf(acc[im][nj][3] * alpha + b1);
            } else {
                float2 v0 = { acc[im][nj][0] * alpha, acc[im][nj][1] * alpha };
                float2 v1 = { acc[im][nj][2] * alpha, acc[im][nj][3] * alpha };
                *(float2*)&C[(long long)r0 * ldc + c0]       = v0;
                *(float2*)&C[(long long)(r0 + 8) * ldc + c0] = v1;
            }
        }
    }
}

// ----------------------------- aux kernels ---------------------------------

// xr[row, PERMC(col)] = rna(x[row, col])
__global__ void __launch_bounds__(256)
round_perm_k(const float* __restrict__ in, float* __restrict__ out)
{
    const int i = blockIdx.x * 256 + threadIdx.x;
    const int row = i >> 10, col = i & 1023;
    out[((long long)row << 10) | PERMC(col)] = rnaf(in[i]);
}

__global__ void __launch_bounds__(256)
pack_bias_k(const float* __restrict__ bq, const float* __restrict__ bk,
            const float* __restrict__ bv, float* __restrict__ b3)
{
    const int i = blockIdx.x * 256 + threadIdx.x;
    if (i < N3)
        b3[i] = (i < DIM) ? bq[i] : (i < 2 * DIM) ? bk[i - DIM] : bv[i - 2 * DIM];
}

__device__ __forceinline__ int P32(int i) { return (i & 16) | P16(i & 15); }

// out[(bx+a)*ldout + by + b] = f(in[(by+P32(b))*ldin + bx + (permCol?P32(a):a)])
__global__ void __launch_bounds__(256)
transpose_perm_k(const float* __restrict__ in, float* __restrict__ out,
                 int ldin, int ldout, long long sIn, long long sOut,
                 int do_rna, int permCol)
{
    __shared__ float tsm[32][33];
    in  += (long long)blockIdx.z * sIn;
    out += (long long)blockIdx.z * sOut;
    const int bx = blockIdx.x * 32, by = blockIdx.y * 32;
    const int tx = threadIdx.x & 31, ty = threadIdx.x >> 5;
#pragma unroll
    for (int d = 0; d < 4; ++d) {
        const int r = ty + d * 8;
        const int ir = by + P32(r);
        const int ic = bx + (permCol ? P32(tx) : tx);
        float v = in[(long long)ir * ldin + ic];
        if (do_rna) v = rnaf(v);
        tsm[r][tx] = v;
    }
    __syncthreads();
#pragma unroll
    for (int d = 0; d < 4; ++d)
        out[(long long)(bx + ty + d * 8) * ldout + by + tx] = tsm[tx][ty + d * 8];
}

// row softmax over 2048-wide rows; writes rna'd values at k-permuted cols.
__global__ void __launch_bounds__(256)
softmax_rows(float* __restrict__ S)
{
    const long long base = (long long)blockIdx.x * SEQ;
    const int tid = threadIdx.x, lane = tid & 31, wid = tid >> 5;
    float v[8];
    float m = -1e30f;
#pragma unroll
    for (int i = 0; i < 8; ++i) { v[i] = S[base + tid + i * 256]; m = fmaxf(m, v[i]); }
    __shared__ float red[8];
#pragma unroll
    for (int o = 16; o > 0; o >>= 1) m = fmaxf(m, __shfl_xor_sync(0xffffffffu, m, o));
    if (lane == 0) red[wid] = m;
    __syncthreads();
    float mr = red[0];
#pragma unroll
    for (int i = 1; i < 8; ++i) mr = fmaxf(mr, red[i]);
    __syncthreads();
    float s = 0.f;
#pragma unroll
    for (int i = 0; i < 8; ++i) { v[i] = expf(v[i] - mr); s += v[i]; }
#pragma unroll
    for (int o = 16; o > 0; o >>= 1) s += __shfl_xor_sync(0xffffffffu, s, o);
    if (lane == 0) red[wid] = s;
    __syncthreads();                 // also guarantees all reads done before perm writes
    float st = 0.f;
#pragma unroll
    for (int i = 0; i < 8; ++i) st += red[i];
    const float inv = 1.0f / st;
#pragma unroll
    for (int i = 0; i < 8; ++i) {
        const int j = tid + i * 256;
        S[base + PERMC(j)] = rnaf(v[i] * inv);
    }
}

// ------------------------------- launcher ----------------------------------

extern "C" void kernel_launch(void* const* d_in, const int* in_sizes, int n_in,
                              void* d_out, int out_size)
{
    (void)in_sizes; (void)n_in; (void)out_size;
    const float* x  = (const float*)d_in[0];
    const float* Wq = (const float*)d_in[1];
    const float* bq = (const float*)d_in[2];
    const float* Wk = (const float*)d_in[3];
    const float* bk = (const float*)d_in[4];
    const float* Wv = (const float*)d_in[5];
    const float* bv = (const float*)d_in[6];
    float* out = (float*)d_out;

    float *QKVp, *Sp, *Vtp, *Wtp, *b3p;
    cudaGetSymbolAddress((void**)&QKVp, g_QKV);
    cudaGetSymbolAddress((void**)&Sp,   g_S);
    cudaGetSymbolAddress((void**)&Vtp,  g_Vt);
    cudaGetSymbolAddress((void**)&Wtp,  g_Wt);
    cudaGetSymbolAddress((void**)&b3p,  g_b3);

    cudaFuncSetAttribute(gemm_nt, cudaFuncAttributeMaxDynamicSharedMemorySize, SMEM_DYN);

    float* xr = Sp;   // rounded+permuted x lives in g_S until scores GEMM

    // x -> tf32, k-permuted
    round_perm_k<<<MTOT * DIM / 256, 256>>>(x, xr);
    pack_bias_k<<<(N3 + 255) / 256, 256>>>(bq, bk, bv, b3p);

    // Wt[n, P(k)] = rna(W[k, n]) — stacked [3072,1024]
    dim3 tb(256), tgw(DIM / 32, DIM / 32, 1);
    transpose_perm_k<<<tgw, tb>>>(Wq, Wtp + 0 * (size_t)DIM * DIM, DIM, DIM, 0, 0, 1, 0);
    transpose_perm_k<<<tgw, tb>>>(Wk, Wtp + 1 * (size_t)DIM * DIM, DIM, DIM, 0, 0, 1, 0);
    transpose_perm_k<<<tgw, tb>>>(Wv, Wtp + 2 * (size_t)DIM * DIM, DIM, DIM, 0, 0, 1, 0);

    dim3 blk(256);

    // fused QKV: [16384,1024] @ [3072,1024]^T -> [16384,3072] (rna + perm cols)
    dim3 gq(N3 / BN, MTOT / BM, 1);
    gemm_nt<<<gq, blk, SMEM_DYN>>>(xr, Wtp, b3p, QKVp,
                                   DIM, DIM, N3, 1.f, 1, DIM / BK, 0, 0, 0);

    // scores = Q @ K^T / 32 per batch
    dim3 gs(SEQ / BN, SEQ / BM, BATCH);
    gemm_nt<<<gs, blk, SMEM_DYN>>>(QKVp, QKVp + DIM, nullptr, Sp,
                                   N3, N3, SEQ, 0.03125f, 0, DIM / BK,
                                   (long long)SEQ * N3, (long long)SEQ * N3,
                                   (long long)SEQ * SEQ);

    // softmax rows (rna + perm cols)
    softmax_rows<<<BATCH * SEQ, 256>>>(Sp);

    // Vt[d, P(t)] = V[t, d] per batch (V cols already permuted in storage)
    dim3 gv(DIM / 32, SEQ / 32, BATCH);
    transpose_perm_k<<<gv, tb>>>(QKVp + 2 * DIM, Vtp, N3, SEQ,
                                 (long long)SEQ * N3, (long long)DIM * SEQ, 0, 1);

    // out = A @ V per batch
    dim3 go(DIM / BN, SEQ / BM, BATCH);
    gemm_nt<<<go, blk, SMEM_DYN>>>(Sp, Vtp, nullptr, out,
                                   SEQ, SEQ, DIM, 1.f, 0, SEQ / BK,
                                   (long long)SEQ * SEQ, (long long)DIM * SEQ,
                                   (long long)SEQ * DIM);
}

// round 4
// speedup vs baseline: 2.1769x; 1.8748x over previous
#include <cuda_runtime.h>
#include <cuda_fp16.h>
#include <cstdint>

// ---------------------------------------------------------------------------
// Fused single-head attention, fp32 in/out. fp16 mma.sync (m16n8k16) GEMMs
// with fp32 accumulation, ldmatrix fragments, cp.async multistage pipeline.
//   B=8, S=2048, D=1024
// ---------------------------------------------------------------------------

#define BATCH 8
#define SEQ   2048
#define DIM   1024
#define MTOT  (BATCH * SEQ)      // 16384
#define N3    (3 * DIM)          // 3072

#define BM 128
#define BN 256
#define BK 32
#define NST 4
#define STAGE_BYTES 24576        // A 128*64B + B 256*64B
#define SMEM_DYN (NST * STAGE_BYTES)

// scratch (device globals — no cudaMalloc allowed)
__device__ __half g_xh[(size_t)MTOT * DIM];        // x in fp16
__device__ __half g_Wt[3 * (size_t)DIM * DIM];     // W^T fp16, [3072,1024]
__device__ __half g_QKV[(size_t)MTOT * N3];        // Q|K|V fp16, ld=3072
__device__ float  g_S[(size_t)BATCH * SEQ * SEQ];  // scores fp32
__device__ __half g_A[(size_t)BATCH * SEQ * SEQ];  // softmax(A) fp16
__device__ __half g_Vt[(size_t)BATCH * DIM * SEQ]; // V^T fp16 per batch
__device__ float  g_b3[N3];

__device__ __forceinline__ uint32_t smem_u32(const void* p) {
    uint32_t a;
    asm("{ .reg .u64 t; cvta.to.shared.u64 t, %1; cvt.u32.u64 %0, t; }" : "=r"(a) : "l"(p));
    return a;
}

__device__ __forceinline__ void cp_async16(uint32_t dst, const void* src) {
    asm volatile("cp.async.cg.shared.global [%0], [%1], 16;" :: "r"(dst), "l"(src) : "memory");
}
#define CP_COMMIT() asm volatile("cp.async.commit_group;" ::: "memory")
#define CP_WAIT2()  asm volatile("cp.async.wait_group 2;" ::: "memory")

__device__ __forceinline__ void ldsm4(uint32_t* r, uint32_t addr) {
    asm volatile("ldmatrix.sync.aligned.m8n8.x4.shared.b16 {%0,%1,%2,%3}, [%4];"
        : "=r"(r[0]), "=r"(r[1]), "=r"(r[2]), "=r"(r[3]) : "r"(addr));
}

__device__ __forceinline__ void mma16(float* c, const uint32_t* a, uint32_t b0, uint32_t b1) {
    asm volatile(
        "mma.sync.aligned.m16n8k16.row.col.f32.f16.f16.f32 "
        "{%0,%1,%2,%3}, {%4,%5,%6,%7}, {%8,%9}, {%0,%1,%2,%3};"
        : "+f"(c[0]), "+f"(c[1]), "+f"(c[2]), "+f"(c[3])
        : "r"(a[0]), "r"(a[1]), "r"(a[2]), "r"(a[3]), "r"(b0), "r"(b1));
}

// smem tile: rows of 64B (32 halves). 16B-chunk swizzle: c ^= (row>>1)&3
// (verified conflict-free for both the 8-lane ldmatrix phases and cp.async fill)
__device__ __forceinline__ uint32_t sw_off(int row, int kc) {
    return (uint32_t)(row * 64 + ((kc ^ ((row >> 1) & 3)) << 4));
}

// ldmatrix lane address for a 16x16 (rows x k) tile at rowbase, k-step ks(0/1)
__device__ __forceinline__ uint32_t ldsm_addr(uint32_t base, int rowbase, int ks, int lane) {
    const int row = rowbase + (lane & 7) + (lane & 8);
    const int kc = 2 * ks + ((lane >> 4) & 1);
    return base + sw_off(row, kc);
}

// ------------------------------ GEMM ---------------------------------------
// C[M,N] = alpha * A[M,K] @ B[N,K]^T (+bias).  A,B fp16 K-major.
// out_half: 1 -> C half, 0 -> C float.   K = nk*32. M%128==0, N%256==0.
__global__ void __launch_bounds__(256, 1)
gemm_nt_h(const __half* __restrict__ A, const __half* __restrict__ B,
          const float* __restrict__ bias, void* __restrict__ Cv,
          int lda, int ldb, int ldc, float alpha, int out_half, int nk,
          long long sA, long long sB, long long sC)
{
    extern __shared__ char smem[];
    A += (long long)blockIdx.z * sA;
    B += (long long)blockIdx.z * sB;

    const int bm = blockIdx.y * BM;
    const int bn = blockIdx.x * BN;
    const int tid  = threadIdx.x;
    const int lane = tid & 31;
    const int wid  = tid >> 5;
    const int wm = wid & 1;      // 2 warps over M (64 rows)
    const int wn = wid >> 1;     // 4 warps over N (64 cols)
    const int g = lane >> 2;
    const int t = lane & 3;

    const uint32_t sb0 = smem_u32(smem);

    // producer: A 512 chunks (2/thread), B 1024 chunks (4/thread); chunk=16B=8 halves
    auto produce = [&](int i) {
        const int k0 = i * BK;
        const uint32_t st = sb0 + (uint32_t)(i & (NST - 1)) * STAGE_BYTES;
#pragma unroll
        for (int j = 0; j < 2; ++j) {
            const int c = tid * 2 + j, row = c >> 2, kc = c & 3;
            cp_async16(st + sw_off(row, kc),
                       A + (long long)(bm + row) * lda + k0 + kc * 8);
        }
#pragma unroll
        for (int j = 0; j < 4; ++j) {
            const int c = tid * 4 + j, row = c >> 2, kc = c & 3;
            cp_async16(st + 8192u + sw_off(row, kc),
                       B + (long long)(bn + row) * ldb + k0 + kc * 8);
        }
    };

    float acc[4][8][4];
#pragma unroll
    for (int i = 0; i < 4; ++i)
#pragma unroll
        for (int j = 0; j < 8; ++j)
#pragma unroll
            for (int q = 0; q < 4; ++q) acc[i][j][q] = 0.f;

#pragma unroll
    for (int s = 0; s < 3; ++s) {
        if (s < nk) produce(s);
        CP_COMMIT();
    }

    for (int i = 0; i < nk; ++i) {
        CP_WAIT2();
        __syncthreads();
        if (i + 3 < nk) produce(i + 3);
        CP_COMMIT();

        const uint32_t st = sb0 + (uint32_t)(i & (NST - 1)) * STAGE_BYTES;
#pragma unroll
        for (int ks = 0; ks < 2; ++ks) {
            uint32_t av[4][4], bv[4][4];
#pragma unroll
            for (int mt = 0; mt < 4; ++mt)
                ldsm4(av[mt], ldsm_addr(st, wm * 64 + mt * 16, ks, lane));
#pragma unroll
            for (int nt = 0; nt < 4; ++nt)
                ldsm4(bv[nt], ldsm_addr(st + 8192u, wn * 64 + nt * 16, ks, lane));
#pragma unroll
            for (int mt = 0; mt < 4; ++mt)
#pragma unroll
                for (int nt = 0; nt < 4; ++nt) {
                    mma16(acc[mt][2 * nt],     av[mt], bv[nt][0], bv[nt][2]);
                    mma16(acc[mt][2 * nt + 1], av[mt], bv[nt][1], bv[nt][3]);
                }
        }
    }

    // epilogue
    if (out_half) {
        __half* C = (__half*)Cv + (long long)blockIdx.z * sC;
#pragma unroll
        for (int im = 0; im < 4; ++im) {
            const int r0 = bm + wm * 64 + im * 16 + g;
#pragma unroll
            for (int nj = 0; nj < 8; ++nj) {
                const int c0 = bn + wn * 64 + nj * 8 + 2 * t;
                const float b0 = bias ? __ldg(bias + c0) : 0.f;
                const float b1 = bias ? __ldg(bias + c0 + 1) : 0.f;
                *(__half2*)&C[(long long)r0 * ldc + c0] =
                    __floats2half2_rn(acc[im][nj][0] * alpha + b0,
                                      acc[im][nj][1] * alpha + b1);
                *(__half2*)&C[(long long)(r0 + 8) * ldc + c0] =
                    __floats2half2_rn(acc[im][nj][2] * alpha + b0,
                                      acc[im][nj][3] * alpha + b1);
            }
        }
    } else {
        float* C = (float*)Cv + (long long)blockIdx.z * sC;
#pragma unroll
        for (int im = 0; im < 4; ++im) {
            const int r0 = bm + wm * 64 + im * 16 + g;
#pragma unroll
            for (int nj = 0; nj < 8; ++nj) {
                const int c0 = bn + wn * 64 + nj * 8 + 2 * t;
                float2 v0 = { acc[im][nj][0] * alpha, acc[im][nj][1] * alpha };
                float2 v1 = { acc[im][nj][2] * alpha, acc[im][nj][3] * alpha };
                *(float2*)&C[(long long)r0 * ldc + c0]       = v0;
                *(float2*)&C[(long long)(r0 + 8) * ldc + c0] = v1;
            }
        }
    }
}

// ----------------------------- aux kernels ---------------------------------

__global__ void __launch_bounds__(256)
f2h_k(const float2* __restrict__ in, __half2* __restrict__ out, int n2)
{
    const int i = blockIdx.x * 256 + threadIdx.x;
    if (i < n2) {
        float2 v = in[i];
        out[i] = __floats2half2_rn(v.x, v.y);
    }
}

__global__ void __launch_bounds__(256)
pack_bias_k(const float* __restrict__ bq, const float* __restrict__ bk,
            const float* __restrict__ bv, float* __restrict__ b3)
{
    const int i = blockIdx.x * 256 + threadIdx.x;
    if (i < N3)
        b3[i] = (i < DIM) ? bq[i] : (i < 2 * DIM) ? bk[i - DIM] : bv[i - 2 * DIM];
}

// out[n][k] = (half) in[k][n], square 1024x1024
__global__ void __launch_bounds__(256)
tr_f2h(const float* __restrict__ in, __half* __restrict__ out)
{
    __shared__ float tsm[32][33];
    const int bx = blockIdx.x * 32, by = blockIdx.y * 32;
    const int tx = threadIdx.x & 31, ty = threadIdx.x >> 5;
#pragma unroll
    for (int d = 0; d < 4; ++d)
        tsm[ty + d * 8][tx] = in[(long long)(by + ty + d * 8) * DIM + bx + tx];
    __syncthreads();
#pragma unroll
    for (int d = 0; d < 4; ++d)
        out[(long long)(bx + ty + d * 8) * DIM + by + tx] =
            __float2half_rn(tsm[tx][ty + d * 8]);
}

// out[d][t] = in[t][d] per batch z (half -> half)
__global__ void __launch_bounds__(256)
tr_h2h(const __half* __restrict__ in, __half* __restrict__ out,
       int ldin, int ldout, long long sIn, long long sOut)
{
    __shared__ __half tsm[32][33];
    in  += (long long)blockIdx.z * sIn;
    out += (long long)blockIdx.z * sOut;
    const int bx = blockIdx.x * 32, by = blockIdx.y * 32;
    const int tx = threadIdx.x & 31, ty = threadIdx.x >> 5;
#pragma unroll
    for (int d = 0; d < 4; ++d)
        tsm[ty + d * 8][tx] = in[(long long)(by + ty + d * 8) * ldin + bx + tx];
    __syncthreads();
#pragma unroll
    for (int d = 0; d < 4; ++d)
        out[(long long)(bx + ty + d * 8) * ldout + by + tx] = tsm[tx][ty + d * 8];
}

// row softmax over fp32 scores (2048/row), writes fp16 A
__global__ void __launch_bounds__(256)
softmax_rows(const float* __restrict__ S, __half* __restrict__ A)
{
    const long long base = (long long)blockIdx.x * SEQ;
    const int tid = threadIdx.x, lane = tid & 31, wid = tid >> 5;
    float v[8];
    float m = -1e30f;
#pragma unroll
    for (int i = 0; i < 8; ++i) { v[i] = S[base + tid + i * 256]; m = fmaxf(m, v[i]); }
    __shared__ float red[8];
#pragma unroll
    for (int o = 16; o > 0; o >>= 1) m = fmaxf(m, __shfl_xor_sync(0xffffffffu, m, o));
    if (lane == 0) red[wid] = m;
    __syncthreads();
    float mr = red[0];
#pragma unroll
    for (int i = 1; i < 8; ++i) mr = fmaxf(mr, red[i]);
    __syncthreads();
    float s = 0.f;
#pragma unroll
    for (int i = 0; i < 8; ++i) { v[i] = expf(v[i] - mr); s += v[i]; }
#pragma unroll
    for (int o = 16; o > 0; o >>= 1) s += __shfl_xor_sync(0xffffffffu, s, o);
    if (lane == 0) red[wid] = s;
    __syncthreads();
    float st = 0.f;
#pragma unroll
    for (int i = 0; i < 8; ++i) st += red[i];
    const float inv = 1.0f / st;
#pragma unroll
    for (int i = 0; i < 8; ++i)
        A[base + tid + i * 256] = __float2half_rn(v[i] * inv);
}

// ------------------------------- launcher ----------------------------------

extern "C" void kernel_launch(void* const* d_in, const int* in_sizes, int n_in,
                              void* d_out, int out_size)
{
    (void)in_sizes; (void)n_in; (void)out_size;
    const float* x  = (const float*)d_in[0];
    const float* Wq = (const float*)d_in[1];
    const float* bq = (const float*)d_in[2];
    const float* Wk = (const float*)d_in[3];
    const float* bk = (const float*)d_in[4];
    const float* Wv = (const float*)d_in[5];
    const float* bv = (const float*)d_in[6];
    float* out = (float*)d_out;

    __half *xh, *Wt, *QKV, *Ap, *Vt;
    float *Sp, *b3;
    cudaGetSymbolAddress((void**)&xh,  g_xh);
    cudaGetSymbolAddress((void**)&Wt,  g_Wt);
    cudaGetSymbolAddress((void**)&QKV, g_QKV);
    cudaGetSymbolAddress((void**)&Sp,  g_S);
    cudaGetSymbolAddress((void**)&Ap,  g_A);
    cudaGetSymbolAddress((void**)&Vt,  g_Vt);
    cudaGetSymbolAddress((void**)&b3,  g_b3);

    cudaFuncSetAttribute(gemm_nt_h, cudaFuncAttributeMaxDynamicSharedMemorySize, SMEM_DYN);

    // x -> fp16
    f2h_k<<<MTOT * DIM / 512, 256>>>((const float2*)x, (__half2*)xh, MTOT * DIM / 2);
    pack_bias_k<<<(N3 + 255) / 256, 256>>>(bq, bk, bv, b3);

    // W^T -> fp16 (stacked [3072,1024])
    dim3 tb(256), tgw(DIM / 32, DIM / 32, 1);
    tr_f2h<<<tgw, tb>>>(Wq, Wt + 0 * (size_t)DIM * DIM);
    tr_f2h<<<tgw, tb>>>(Wk, Wt + 1 * (size_t)DIM * DIM);
    tr_f2h<<<tgw, tb>>>(Wv, Wt + 2 * (size_t)DIM * DIM);

    dim3 blk(256);

    // fused QKV: [16384,1024] @ [3072,1024]^T -> half [16384,3072] + bias
    dim3 gq(N3 / BN, MTOT / BM, 1);
    gemm_nt_h<<<gq, blk, SMEM_DYN>>>(xh, Wt, b3, QKV,
                                     DIM, DIM, N3, 1.f, 1, DIM / BK, 0, 0, 0);

    // scores = Q @ K^T / 32 per batch -> fp32
    dim3 gs(SEQ / BN, SEQ / BM, BATCH);
    gemm_nt_h<<<gs, blk, SMEM_DYN>>>(QKV, QKV + DIM, nullptr, Sp,
                                     N3, N3, SEQ, 0.03125f, 0, DIM / BK,
                                     (long long)SEQ * N3, (long long)SEQ * N3,
                                     (long long)SEQ * SEQ);

    // softmax -> fp16 A
    softmax_rows<<<BATCH * SEQ, 256>>>(Sp, Ap);

    // V^T per batch
    dim3 gv(DIM / 32, SEQ / 32, BATCH);
    tr_h2h<<<gv, tb>>>(QKV + 2 * DIM, Vt, N3, SEQ,
                       (long long)SEQ * N3, (long long)DIM * SEQ);

    // out = A @ V per batch -> fp32
    dim3 go(DIM / BN, SEQ / BM, BATCH);
    gemm_nt_h<<<go, blk, SMEM_DYN>>>(Ap, Vt, nullptr, out,
                                     SEQ, SEQ, DIM, 1.f, 0, SEQ / BK,
                                     (long long)SEQ * SEQ, (long long)DIM * SEQ,
                                     (long long)SEQ * DIM);
}

// round 5
// speedup vs baseline: 2.4886x; 1.1432x over previous
#include <cuda_runtime.h>
#include <cuda_fp16.h>
#include <cstdint>

// ---------------------------------------------------------------------------
// Fused single-head attention, fp32 in/out. fp16 mma.sync (m16n8k16) GEMMs,
// warp-specialized producer (cp.async + mbarrier ring), ldmatrix consumers.
//   B=8, S=2048, D=1024
// ---------------------------------------------------------------------------

#define BATCH 8
#define SEQ   2048
#define DIM   1024
#define MTOT  (BATCH * SEQ)      // 16384
#define N3    (3 * DIM)          // 3072

#define BM 128
#define BN 256
#define BK 32
#define NST 4
#define STAGE_BYTES 24576        // A 128*64B + B 256*64B
#define SMEM_DYN (NST * STAGE_BYTES)
#define NTHREADS 320             // 8 compute warps + 2 producer warps

// scratch (device globals — no cudaMalloc allowed)
__device__ __half g_xh[(size_t)MTOT * DIM];
__device__ __half g_Wt[3 * (size_t)DIM * DIM];
__device__ __half g_QKV[(size_t)MTOT * N3];
__device__ float  g_S[(size_t)BATCH * SEQ * SEQ];
__device__ __half g_A[(size_t)BATCH * SEQ * SEQ];
__device__ __half g_Vt[(size_t)BATCH * DIM * SEQ];
__device__ float  g_b3[N3];

__device__ __forceinline__ uint32_t smem_u32(const void* p) {
    uint32_t a;
    asm("{ .reg .u64 t; cvta.to.shared.u64 t, %1; cvt.u32.u64 %0, t; }" : "=r"(a) : "l"(p));
    return a;
}

__device__ __forceinline__ void cp_async16(uint32_t dst, const void* src) {
    asm volatile("cp.async.cg.shared.global [%0], [%1], 16;" :: "r"(dst), "l"(src) : "memory");
}

__device__ __forceinline__ void cp_async_arrive(uint32_t mbar) {
    asm volatile("cp.async.mbarrier.arrive.noinc.shared::cta.b64 [%0];" :: "r"(mbar) : "memory");
}

#define MB_INIT(addr, cnt) \
    asm volatile("mbarrier.init.shared.b64 [%0], %1;" :: "r"(addr), "r"((uint32_t)(cnt)) : "memory")

#define MB_ARRIVE(addr) \
    asm volatile("mbarrier.arrive.shared.b64 _, [%0];" :: "r"(addr) : "memory")

#define MB_WAIT_PARITY(addr, parity) do {                                              \
    uint32_t _m = (addr); uint32_t _p = (parity); uint32_t _d;                         \
    asm volatile("{ .reg .pred p; mbarrier.try_wait.parity.acquire.cta.shared::cta.b64 p, [%1], %2; selp.b32 %0, 1, 0, p; }" \
                 : "=r"(_d) : "r"(_m), "r"(_p) : "memory");                            \
    while (!_d) {                                                                      \
        asm volatile("{ .reg .pred p; mbarrier.try_wait.parity.acquire.cta.shared::cta.b64 p, [%1], %2, 0x989680; selp.b32 %0, 1, 0, p; }" \
                     : "=r"(_d) : "r"(_m), "r"(_p) : "memory");                        \
    }                                                                                  \
} while (0)

__device__ __forceinline__ void ldsm4(uint32_t* r, uint32_t addr) {
    asm volatile("ldmatrix.sync.aligned.m8n8.x4.shared.b16 {%0,%1,%2,%3}, [%4];"
        : "=r"(r[0]), "=r"(r[1]), "=r"(r[2]), "=r"(r[3]) : "r"(addr));
}

__device__ __forceinline__ void mma16(float* c, const uint32_t* a, uint32_t b0, uint32_t b1) {
    asm volatile(
        "mma.sync.aligned.m16n8k16.row.col.f32.f16.f16.f32 "
        "{%0,%1,%2,%3}, {%4,%5,%6,%7}, {%8,%9}, {%0,%1,%2,%3};"
        : "+f"(c[0]), "+f"(c[1]), "+f"(c[2]), "+f"(c[3])
        : "r"(a[0]), "r"(a[1]), "r"(a[2]), "r"(a[3]), "r"(b0), "r"(b1));
}

// smem tile rows of 64B (32 halves); 16B-chunk swizzle c ^= (row>>1)&3
__device__ __forceinline__ uint32_t sw_off(int row, int kc) {
    return (uint32_t)(row * 64 + ((kc ^ ((row >> 1) & 3)) << 4));
}
__device__ __forceinline__ uint32_t ldsm_addr(uint32_t base, int rowbase, int ks, int lane) {
    const int row = rowbase + (lane & 7) + (lane & 8);
    const int kc = 2 * ks + ((lane >> 4) & 1);
    return base + sw_off(row, kc);
}

// ------------------------------ GEMM ---------------------------------------
// C[M,N] = alpha * A[M,K] @ B[N,K]^T (+bias). A,B fp16 K-major.
// out_half: 1 -> C half, 0 -> C float. K = nk*32. M%128==0, N%256==0.
__global__ void __launch_bounds__(NTHREADS, 1)
gemm_nt_h(const __half* __restrict__ A, const __half* __restrict__ B,
          const float* __restrict__ bias, void* __restrict__ Cv,
          int lda, int ldb, int ldc, float alpha, int out_half, int nk,
          long long sA, long long sB, long long sC)
{
    extern __shared__ char smem[];
    __shared__ __align__(8) unsigned long long mbar[2 * NST];  // full[0..3], empty[4..7]

    A += (long long)blockIdx.z * sA;
    B += (long long)blockIdx.z * sB;

    const int bm = blockIdx.y * BM;
    const int bn = blockIdx.x * BN;
    const int tid  = threadIdx.x;
    const int lane = tid & 31;
    const int wid  = tid >> 5;

    const uint32_t sb0 = smem_u32(smem);
    const uint32_t mb  = smem_u32(&mbar[0]);   // full[s]=mb+8s, empty[s]=mb+32+8s

    if (tid == 0) {
#pragma unroll
        for (int s = 0; s < NST; ++s) {
            MB_INIT(mb + 8 * s, 64);        // full: 64 producer threads
            MB_INIT(mb + 32 + 8 * s, 256);  // empty: 256 compute threads
        }
    }
    __syncthreads();

    if (wid >= 8) {
        // ------------------------- producer warps --------------------------
        const int pt = tid - 256;   // 0..63
        for (int i = 0; i < nk; ++i) {
            const int s = i & (NST - 1);
            const int u = i >> 2;
            if (u > 0) MB_WAIT_PARITY(mb + 32 + 8 * s, (uint32_t)((u - 1) & 1));
            const uint32_t st = sb0 + (uint32_t)s * STAGE_BYTES;
            const int k0 = i * BK;
#pragma unroll
            for (int j = 0; j < 8; ++j) {          // A: 512 chunks, 8/thread
                const int c = pt * 8 + j, row = c >> 2, kc = c & 3;
                cp_async16(st + sw_off(row, kc),
                           A + (long long)(bm + row) * lda + k0 + kc * 8);
            }
#pragma unroll
            for (int j = 0; j < 16; ++j) {         // B: 1024 chunks, 16/thread
                const int c = pt * 16 + j, row = c >> 2, kc = c & 3;
                cp_async16(st + 8192u + sw_off(row, kc),
                           B + (long long)(bn + row) * ldb + k0 + kc * 8);
            }
            cp_async_arrive(mb + 8 * s);
        }
        return;
    }

    // --------------------------- compute warps ------------------------------
    const int wm = wid & 1;      // 2 warps over M (64 rows)
    const int wn = wid >> 1;     // 4 warps over N (64 cols)
    const int g = lane >> 2;
    const int t = lane & 3;

    float acc[4][8][4];
#pragma unroll
    for (int i = 0; i < 4; ++i)
#pragma unroll
        for (int j = 0; j < 8; ++j)
#pragma unroll
            for (int q = 0; q < 4; ++q) acc[i][j][q] = 0.f;

    for (int i = 0; i < nk; ++i) {
        const int s = i & (NST - 1);
        const int u = i >> 2;
        MB_WAIT_PARITY(mb + 8 * s, (uint32_t)(u & 1));
        const uint32_t st = sb0 + (uint32_t)s * STAGE_BYTES;
#pragma unroll
        for (int ks = 0; ks < 2; ++ks) {
            uint32_t av[4][4], bv[4][4];
#pragma unroll
            for (int mt = 0; mt < 4; ++mt)
                ldsm4(av[mt], ldsm_addr(st, wm * 64 + mt * 16, ks, lane));
#pragma unroll
            for (int nt = 0; nt < 4; ++nt)
                ldsm4(bv[nt], ldsm_addr(st + 8192u, wn * 64 + nt * 16, ks, lane));
#pragma unroll
            for (int mt = 0; mt < 4; ++mt)
#pragma unroll
                for (int nt = 0; nt < 4; ++nt) {
                    mma16(acc[mt][2 * nt],     av[mt], bv[nt][0], bv[nt][2]);
                    mma16(acc[mt][2 * nt + 1], av[mt], bv[nt][1], bv[nt][3]);
                }
        }
        MB_ARRIVE(mb + 32 + 8 * s);
    }

    // epilogue
    if (out_half) {
        __half* C = (__half*)Cv + (long long)blockIdx.z * sC;
#pragma unroll
        for (int im = 0; im < 4; ++im) {
            const int r0 = bm + wm * 64 + im * 16 + g;
#pragma unroll
            for (int nj = 0; nj < 8; ++nj) {
                const int c0 = bn + wn * 64 + nj * 8 + 2 * t;
                const float b0 = bias ? __ldg(bias + c0) : 0.f;
                const float b1 = bias ? __ldg(bias + c0 + 1) : 0.f;
                *(__half2*)&C[(long long)r0 * ldc + c0] =
                    __floats2half2_rn(acc[im][nj][0] * alpha + b0,
                                      acc[im][nj][1] * alpha + b1);
                *(__half2*)&C[(long long)(r0 + 8) * ldc + c0] =
                    __floats2half2_rn(acc[im][nj][2] * alpha + b0,
                                      acc[im][nj][3] * alpha + b1);
            }
        }
    } else {
        float* C = (float*)Cv + (long long)blockIdx.z * sC;
#pragma unroll
        for (int im = 0; im < 4; ++im) {
            const int r0 = bm + wm * 64 + im * 16 + g;
#pragma unroll
            for (int nj = 0; nj < 8; ++nj) {
                const int c0 = bn + wn * 64 + nj * 8 + 2 * t;
                float2 v0 = { acc[im][nj][0] * alpha, acc[im][nj][1] * alpha };
                float2 v1 = { acc[im][nj][2] * alpha, acc[im][nj][3] * alpha };
                *(float2*)&C[(long long)r0 * ldc + c0]       = v0;
                *(float2*)&C[(long long)(r0 + 8) * ldc + c0] = v1;
            }
        }
    }
}

// ----------------------------- aux kernels ---------------------------------

__global__ void __launch_bounds__(256)
f2h_k(const float2* __restrict__ in, __half2* __restrict__ out, int n2)
{
    const int i = blockIdx.x * 256 + threadIdx.x;
    if (i < n2) {
        float2 v = in[i];
        out[i] = __floats2half2_rn(v.x, v.y);
    }
}

__global__ void __launch_bounds__(256)
pack_bias_k(const float* __restrict__ bq, const float* __restrict__ bk,
            const float* __restrict__ bv, float* __restrict__ b3)
{
    const int i = blockIdx.x * 256 + threadIdx.x;
    if (i < N3)
        b3[i] = (i < DIM) ? bq[i] : (i < 2 * DIM) ? bk[i - DIM] : bv[i - 2 * DIM];
}

__global__ void __launch_bounds__(256)
tr_f2h(const float* __restrict__ in, __half* __restrict__ out)
{
    __shared__ float tsm[32][33];
    const int bx = blockIdx.x * 32, by = blockIdx.y * 32;
    const int tx = threadIdx.x & 31, ty = threadIdx.x >> 5;
#pragma unroll
    for (int d = 0; d < 4; ++d)
        tsm[ty + d * 8][tx] = in[(long long)(by + ty + d * 8) * DIM + bx + tx];
    __syncthreads();
#pragma unroll
    for (int d = 0; d < 4; ++d)
        out[(long long)(bx + ty + d * 8) * DIM + by + tx] =
            __float2half_rn(tsm[tx][ty + d * 8]);
}

__global__ void __launch_bounds__(256)
tr_h2h(const __half* __restrict__ in, __half* __restrict__ out,
       int ldin, int ldout, long long sIn, long long sOut)
{
    __shared__ __half tsm[32][33];
    in  += (long long)blockIdx.z * sIn;
    out += (long long)blockIdx.z * sOut;
    const int bx = blockIdx.x * 32, by = blockIdx.y * 32;
    const int tx = threadIdx.x & 31, ty = threadIdx.x >> 5;
#pragma unroll
    for (int d = 0; d < 4; ++d)
        tsm[ty + d * 8][tx] = in[(long long)(by + ty + d * 8) * ldin + bx + tx];
    __syncthreads();
#pragma unroll
    for (int d = 0; d < 4; ++d)
        out[(long long)(bx + ty + d * 8) * ldout + by + tx] = tsm[tx][ty + d * 8];
}

__global__ void __launch_bounds__(256)
softmax_rows(const float* __restrict__ S, __half* __restrict__ A)
{
    const long long base = (long long)blockIdx.x * SEQ;
    const int tid = threadIdx.x, lane = tid & 31, wid = tid >> 5;
    float v[8];
    float m = -1e30f;
#pragma unroll
    for (int i = 0; i < 8; ++i) { v[i] = S[base + tid + i * 256]; m = fmaxf(m, v[i]); }
    __shared__ float red[8];
#pragma unroll
    for (int o = 16; o > 0; o >>= 1) m = fmaxf(m, __shfl_xor_sync(0xffffffffu, m, o));
    if (lane == 0) red[wid] = m;
    __syncthreads();
    float mr = red[0];
#pragma unroll
    for (int i = 1; i < 8; ++i) mr = fmaxf(mr, red[i]);
    __syncthreads();
    float s = 0.f;
#pragma unroll
    for (int i = 0; i < 8; ++i) { v[i] = expf(v[i] - mr); s += v[i]; }
#pragma unroll
    for (int o = 16; o > 0; o >>= 1) s += __shfl_xor_sync(0xffffffffu, s, o);
    if (lane == 0) red[wid] = s;
    __syncthreads();
    float st = 0.f;
#pragma unroll
    for (int i = 0; i < 8; ++i) st += red[i];
    const float inv = 1.0f / st;
#pragma unroll
    for (int i = 0; i < 8; ++i)
        A[base + tid + i * 256] = __float2half_rn(v[i] * inv);
}

// ------------------------------- launcher ----------------------------------

extern "C" void kernel_launch(void* const* d_in, const int* in_sizes, int n_in,
                              void* d_out, int out_size)
{
    (void)in_sizes; (void)n_in; (void)out_size;
    const float* x  = (const float*)d_in[0];
    const float* Wq = (const float*)d_in[1];
    const float* bq = (const float*)d_in[2];
    const float* Wk = (const float*)d_in[3];
    const float* bk = (const float*)d_in[4];
    const float* Wv = (const float*)d_in[5];
    const float* bv = (const float*)d_in[6];
    float* out = (float*)d_out;

    __half *xh, *Wt, *QKV, *Ap, *Vt;
    float *Sp, *b3;
    cudaGetSymbolAddress((void**)&xh,  g_xh);
    cudaGetSymbolAddress((void**)&Wt,  g_Wt);
    cudaGetSymbolAddress((void**)&QKV, g_QKV);
    cudaGetSymbolAddress((void**)&Sp,  g_S);
    cudaGetSymbolAddress((void**)&Ap,  g_A);
    cudaGetSymbolAddress((void**)&Vt,  g_Vt);
    cudaGetSymbolAddress((void**)&b3,  g_b3);

    cudaFuncSetAttribute(gemm_nt_h, cudaFuncAttributeMaxDynamicSharedMemorySize, SMEM_DYN);

    f2h_k<<<MTOT * DIM / 512, 256>>>((const float2*)x, (__half2*)xh, MTOT * DIM / 2);
    pack_bias_k<<<(N3 + 255) / 256, 256>>>(bq, bk, bv, b3);

    dim3 tb(256), tgw(DIM / 32, DIM / 32, 1);
    tr_f2h<<<tgw, tb>>>(Wq, Wt + 0 * (size_t)DIM * DIM);
    tr_f2h<<<tgw, tb>>>(Wk, Wt + 1 * (size_t)DIM * DIM);
    tr_f2h<<<tgw, tb>>>(Wv, Wt + 2 * (size_t)DIM * DIM);

    dim3 blk(NTHREADS);

    // fused QKV: [16384,1024] @ [3072,1024]^T -> half + bias
    dim3 gq(N3 / BN, MTOT / BM, 1);
    gemm_nt_h<<<gq, blk, SMEM_DYN>>>(xh, Wt, b3, QKV,
                                     DIM, DIM, N3, 1.f, 1, DIM / BK, 0, 0, 0);

    // scores = Q @ K^T / 32 per batch -> fp32
    dim3 gs(SEQ / BN, SEQ / BM, BATCH);
    gemm_nt_h<<<gs, blk, SMEM_DYN>>>(QKV, QKV + DIM, nullptr, Sp,
                                     N3, N3, SEQ, 0.03125f, 0, DIM / BK,
                                     (long long)SEQ * N3, (long long)SEQ * N3,
                                     (long long)SEQ * SEQ);

    softmax_rows<<<BATCH * SEQ, 256>>>(Sp, Ap);

    dim3 gv(DIM / 32, SEQ / 32, BATCH);
    tr_h2h<<<gv, tb>>>(QKV + 2 * DIM, Vt, N3, SEQ,
                       (long long)SEQ * N3, (long long)DIM * SEQ);

    dim3 go(DIM / BN, SEQ / BM, BATCH);
    gemm_nt_h<<<go, blk, SMEM_DYN>>>(Ap, Vt, nullptr, out,
                                     SEQ, SEQ, DIM, 1.f, 0, SEQ / BK,
                                     (long long)SEQ * SEQ, (long long)DIM * SEQ,
                                     (long long)SEQ * DIM);
}